// round 6
// baseline (speedup 1.0000x reference)
#include <cuda_runtime.h>
#include <math.h>

// Problem constants (fixed by the dataset)
#define NU 60000
#define NI 40000
#define NN 100000     // NU + NI
#define NE 500000
#define D  64
#define NF 4
#define NBLK 98       // ceil(NN/1024) for the scan

// ---------------- static device scratch ----------------
__device__ float  g_ego0[NN * D];
__device__ float  g_ego1[NN * D];
__device__ float  g_all [NN * D];
__device__ float  g_tv0 [NN * D];    // tv double buffer
__device__ float  g_tv1 [NN * D];
__device__ float4 g_S4  [NE];        // raw S (only written on final iteration)
__device__ float4 g_Ssm4[NE];        // softmaxed S, edge-major
__device__ float  g_rn  [NN * NF];   // per-node per-factor 1/||xn||
__device__ float  g_dinv[NN];
__device__ int    g_deg [NN];
__device__ int    g_rowstart[NN + 1];
__device__ int    g_cnt [NN];
__device__ int    g_blocksum[NBLK];
// adjacency as parallel sequential streams (conv reads these linearly)
__device__ int    g_adjsrc[2 * NE];
__device__ float  g_adjen [2 * NE];
__device__ float4 g_adjsm [2 * NE];  // softmax weights scattered in by score
__device__ int2   g_epos  [NE];      // edge -> {fwd slot, rev slot}

// ---------------- setup kernels ----------------

__global__ void k_initego(const float* __restrict__ u, const float* __restrict__ it) {
    int i = blockIdx.x * blockDim.x + threadIdx.x;
    if (i >= NN * D) return;
    float v = (i < NU * D) ? u[i] : it[i - NU * D];
    g_ego0[i] = v;
    g_all[i]  = v;
}

__global__ void k_deg(const int* __restrict__ ei) {
    int j = blockIdx.x * blockDim.x + threadIdx.x;
    if (j >= NE) return;
    atomicAdd(&g_deg[ei[j]], 1);
    atomicAdd(&g_deg[ei[NE + j]], 1);
}

__global__ void k_dinv() {
    int n = blockIdx.x * blockDim.x + threadIdx.x;
    if (n >= NN) return;
    int d = g_deg[n];
    g_dinv[n] = (d > 0) ? (1.0f / sqrtf((float)d)) : 0.0f;
}

__global__ void k_partial() {
    __shared__ int sh[1024];
    int t = threadIdx.x, n = blockIdx.x * 1024 + t;
    sh[t] = (n < NN) ? g_deg[n] : 0;
    __syncthreads();
    for (int o = 512; o > 0; o >>= 1) {
        if (t < o) sh[t] += sh[t + o];
        __syncthreads();
    }
    if (t == 0) g_blocksum[blockIdx.x] = sh[0];
}

__global__ void k_scanblocks() {
    int acc = 0;
    for (int b = 0; b < NBLK; b++) {
        int v = g_blocksum[b];
        g_blocksum[b] = acc;
        acc += v;
    }
    g_rowstart[NN] = 2 * NE;
}

__global__ void k_offsets() {
    __shared__ int sh[1024];
    int t = threadIdx.x, n = blockIdx.x * 1024 + t;
    int v = (n < NN) ? g_deg[n] : 0;
    sh[t] = v;
    __syncthreads();
    for (int o = 1; o < 1024; o <<= 1) {
        int x = (t >= o) ? sh[t - o] : 0;
        __syncthreads();
        sh[t] += x;
        __syncthreads();
    }
    if (n < NN) g_rowstart[n] = g_blocksum[blockIdx.x] + sh[t] - v;
}

// fill CSR adjacency streams; record each edge's two slots
__global__ void k_fill(const int* __restrict__ ei) {
    int d = blockIdx.x * blockDim.x + threadIdx.x;
    if (d >= 2 * NE) return;
    int j = (d < NE) ? d : d - NE;
    int r = ei[j], c = ei[NE + j];
    int src = (d < NE) ? r : c;
    int dst = (d < NE) ? c : r;
    int pos = g_rowstart[dst] + atomicAdd(&g_cnt[dst], 1);
    g_adjsrc[pos] = src;
    g_adjen[pos]  = g_dinv[src] * g_dinv[dst];
    if (d < NE) g_epos[j].x = pos;
    else        g_epos[j].y = pos;
}

// initial softmax of the input S: write Ssm4 + scatter weights to both slots
__global__ void k_softmax0(const float* __restrict__ S) {
    int j = blockIdx.x * blockDim.x + threadIdx.x;
    if (j >= NE) return;
    float4 s = make_float4(S[j], S[NE + j], S[2 * NE + j], S[3 * NE + j]);
    float m  = fmaxf(fmaxf(s.x, s.y), fmaxf(s.z, s.w));
    float e0 = expf(s.x - m), e1 = expf(s.y - m);
    float e2 = expf(s.z - m), e3 = expf(s.w - m);
    float r  = 1.0f / (e0 + e1 + e2 + e3);
    float4 sm = make_float4(e0 * r, e1 * r, e2 * r, e3 * r);
    g_Ssm4[j] = sm;
    int2 ep = g_epos[j];
    g_adjsm[ep.x] = sm;
    g_adjsm[ep.y] = sm;
}

// tv for layer 0 from the initial ego (warp per node)
__global__ void k_tv0() {
    int gw = (blockIdx.x * blockDim.x + threadIdx.x) >> 5;
    if (gw >= NN) return;
    int lane = threadIdx.x & 31;
    float2 a = reinterpret_cast<const float2*>(g_ego0 + (size_t)gw * D)[lane];
    float ss = a.x * a.x + a.y * a.y;
    ss += __shfl_xor_sync(0xFFFFFFFF, ss, 1);
    ss += __shfl_xor_sync(0xFFFFFFFF, ss, 2);
    ss += __shfl_xor_sync(0xFFFFFFFF, ss, 4);
    float rinv = 1.0f / fmaxf(sqrtf(ss), 1e-12f);
    float2 o;
    o.x = tanhf(a.x * rinv);
    o.y = tanhf(a.y * rinv);
    reinterpret_cast<float2*>(g_tv0 + (size_t)gw * D)[lane] = o;
}

// ---------------- main iteration kernels ----------------

// CSR conv, one warp per destination node. All adjacency data arrives as
// independent sequential streams (src, enorm, sm4); only src->ego is a
// dependent gather. 2-deep prefetch.
template <bool LAST>
__global__ void k_conv(const float* __restrict__ ego, float* __restrict__ xn,
                       float* __restrict__ tv_next) {
    int gw = (blockIdx.x * blockDim.x + threadIdx.x) >> 5;
    if (gw >= NN) return;
    int lane = threadIdx.x & 31;
    int kf = lane >> 3;
    int s = g_rowstart[gw], e = g_rowstart[gw + 1];

    float2 acc = make_float2(0.0f, 0.0f);

    int    src0 = 0,    src1 = 0;
    float  en0  = 0.0f, en1  = 0.0f;
    float4 sm0  = make_float4(0, 0, 0, 0), sm1 = sm0;
    if (s < e) {
        src0 = g_adjsrc[s]; en0 = g_adjen[s]; sm0 = g_adjsm[s];
    }
    if (s + 1 < e) {
        src1 = g_adjsrc[s + 1]; en1 = g_adjen[s + 1]; sm1 = g_adjsm[s + 1];
    }
    for (int i = s; i < e; i++) {
        // issue the gather for the current entry immediately
        float2 v = reinterpret_cast<const float2*>(ego + (size_t)src0 * D)[lane];
        float smk = (kf == 0) ? sm0.x : (kf == 1) ? sm0.y : (kf == 2) ? sm0.z : sm0.w;
        float w = en0 * smk;
        // rotate pipeline and prefetch i+2
        src0 = src1; en0 = en1; sm0 = sm1;
        if (i + 2 < e) {
            src1 = g_adjsrc[i + 2]; en1 = g_adjen[i + 2]; sm1 = g_adjsm[i + 2];
        }
        acc.x += w * v.x;
        acc.y += w * v.y;
    }

    reinterpret_cast<float2*>(xn + (size_t)gw * D)[lane] = acc;

    // per-factor inverse norm (groups of 8 lanes)
    float ss = acc.x * acc.x + acc.y * acc.y;
    ss += __shfl_xor_sync(0xFFFFFFFF, ss, 1);
    ss += __shfl_xor_sync(0xFFFFFFFF, ss, 2);
    ss += __shfl_xor_sync(0xFFFFFFFF, ss, 4);
    float rinv = 1.0f / fmaxf(sqrtf(ss), 1e-12f);
    if ((lane & 7) == 0) g_rn[gw * NF + kf] = rinv;

    if (LAST) {
        float2* ap = reinterpret_cast<float2*>(g_all + (size_t)gw * D) + lane;
        float2 av = *ap;
        av.x += acc.x; av.y += acc.y;
        *ap = av;
        float2 t;
        t.x = tanhf(acc.x * rinv);
        t.y = tanhf(acc.y * rinv);
        reinterpret_cast<float2*>(tv_next + (size_t)gw * D)[lane] = t;
    }
}

// routing-score update + fused softmax for the NEXT conv.
// sv = Ssm[j] + rn[row]_k * dot(xn[row,k,:], tv[col,k,:])
// FINAL: write raw S only. Otherwise: write Ssm4 + scatter weights to adj.
template <bool FINAL>
__global__ void k_score(const float* __restrict__ xn, const float* __restrict__ tv,
                        const int* __restrict__ ei) {
    int gw = (blockIdx.x * blockDim.x + threadIdx.x) >> 5;
    if (gw >= NE) return;
    int lane = threadIdx.x & 31;
    int r = ei[gw];
    int c = ei[NE + gw];
    float2 a = reinterpret_cast<const float2*>(xn + (size_t)r * D)[lane];
    float2 b = reinterpret_cast<const float2*>(tv + (size_t)c * D)[lane];
    float p = a.x * b.x + a.y * b.y;
    p += __shfl_xor_sync(0xFFFFFFFF, p, 1);
    p += __shfl_xor_sync(0xFFFFFFFF, p, 2);
    p += __shfl_xor_sync(0xFFFFFFFF, p, 4);
    float p0 = __shfl_sync(0xFFFFFFFF, p, 0);
    float p1 = __shfl_sync(0xFFFFFFFF, p, 8);
    float p2 = __shfl_sync(0xFFFFFFFF, p, 16);
    float p3 = __shfl_sync(0xFFFFFFFF, p, 24);
    if (lane == 0) {
        float4 rn = *reinterpret_cast<const float4*>(g_rn + (size_t)r * NF);
        float4 sv = g_Ssm4[gw];
        sv.x += p0 * rn.x;
        sv.y += p1 * rn.y;
        sv.z += p2 * rn.z;
        sv.w += p3 * rn.w;
        if (FINAL) {
            g_S4[gw] = sv;
        } else {
            // softmax(sv) for the next iteration's conv
            float m  = fmaxf(fmaxf(sv.x, sv.y), fmaxf(sv.z, sv.w));
            float e0 = expf(sv.x - m), e1 = expf(sv.y - m);
            float e2 = expf(sv.z - m), e3 = expf(sv.w - m);
            float rr = 1.0f / (e0 + e1 + e2 + e3);
            float4 sm = make_float4(e0 * rr, e1 * rr, e2 * rr, e3 * rr);
            g_Ssm4[gw] = sm;
            int2 ep = g_epos[gw];
            g_adjsm[ep.x] = sm;
            g_adjsm[ep.y] = sm;
        }
    }
}

// output S transpose [NE,4] -> [4,NE]
__global__ void k_transS_out(float* __restrict__ outS) {
    int j = blockIdx.x * blockDim.x + threadIdx.x;
    if (j >= NE) return;
    float4 s = g_S4[j];
    outS[j]          = s.x;
    outS[NE + j]     = s.y;
    outS[2 * NE + j] = s.z;
    outS[3 * NE + j] = s.w;
}

// ---------------- host orchestration ----------------

extern "C" void kernel_launch(void* const* d_in, const int* in_sizes, int n_in,
                              void* d_out, int out_size) {
    const float* user = (const float*)d_in[0];
    const float* item = (const float*)d_in[1];
    const float* Sin  = (const float*)d_in[2];
    const int*   ei   = (const int*)d_in[3];
    float* out = (float*)d_out;

    void *p_deg, *p_cnt, *p_ego0, *p_ego1, *p_all, *p_tv0, *p_tv1;
    cudaGetSymbolAddress(&p_deg,  g_deg);
    cudaGetSymbolAddress(&p_cnt,  g_cnt);
    cudaGetSymbolAddress(&p_ego0, g_ego0);
    cudaGetSymbolAddress(&p_ego1, g_ego1);
    cudaGetSymbolAddress(&p_all,  g_all);
    cudaGetSymbolAddress(&p_tv0,  g_tv0);
    cudaGetSymbolAddress(&p_tv1,  g_tv1);

    const int T = 256;
    const int gElem  = (NN * D + T - 1) / T;
    const int gNode  = (NN + T - 1) / T;
    const int gEdge  = (NE + T - 1) / T;
    const int gDir   = (2 * NE + T - 1) / T;
    const int gEdgeW = (NE * 32 + T - 1) / T;
    const int gNodeW = (NN * 32 + T - 1) / T;

    // ---- setup ----
    cudaMemsetAsync(p_deg, 0, NN * sizeof(int), 0);
    cudaMemsetAsync(p_cnt, 0, NN * sizeof(int), 0);
    k_initego<<<gElem, T>>>(user, item);
    k_deg<<<gEdge, T>>>(ei);
    k_dinv<<<gNode, T>>>();
    k_partial<<<NBLK, 1024>>>();
    k_scanblocks<<<1, 1>>>();
    k_offsets<<<NBLK, 1024>>>();
    k_fill<<<gDir, T>>>(ei);
    k_softmax0<<<gEdge, T>>>(Sin);
    k_tv0<<<gNodeW, T>>>();

    // ---- 2 layers x 2 routing iterations ----
    float* ego = (float*)p_ego0;
    float* xn  = (float*)p_ego1;
    float* tv  = (float*)p_tv0;
    float* tvn = (float*)p_tv1;
    for (int layer = 0; layer < 2; layer++) {
        for (int it = 0; it < 2; it++) {
            if (it == 1)
                k_conv<true><<<gNodeW, T>>>(ego, xn, tvn);  // fused accum + next tv
            else
                k_conv<false><<<gNodeW, T>>>(ego, xn, tvn);
            bool final = (layer == 1 && it == 1);
            if (final)
                k_score<true><<<gEdgeW, T>>>(xn, tv, ei);   // raw S out
            else
                k_score<false><<<gEdgeW, T>>>(xn, tv, ei);  // fused softmax+scatter
        }
        float* t = ego; ego = xn; xn = t;
        t = tv; tv = tvn; tvn = t;
    }

    // ---- output: [user_all | item_all | S(4,NE)] ----
    cudaMemcpyAsync(out, p_all, (size_t)NN * D * sizeof(float),
                    cudaMemcpyDeviceToDevice, 0);
    k_transS_out<<<gEdge, T>>>(out + (size_t)NN * D);
}

// round 7
// speedup vs baseline: 1.4061x; 1.4061x over previous
#include <cuda_runtime.h>
#include <math.h>

// Problem constants (fixed by the dataset)
#define NU 60000
#define NI 40000
#define NN 100000     // NU + NI
#define NE 500000
#define D  64
#define NF 4
#define NBLK 98       // ceil(NN/1024) for the scan

// ---------------- static device scratch ----------------
__device__ float  g_ego0[NN * D];
__device__ float  g_ego1[NN * D];
__device__ float  g_all [NN * D];
__device__ float  g_tv0 [NN * D];    // tv double buffer
__device__ float  g_tv1 [NN * D];
__device__ float4 g_S4  [NE];        // raw S (written only on the final iteration)
__device__ float4 g_SsmA[NE];        // softmax(S) double buffer
__device__ float4 g_SsmB[NE];
__device__ float  g_dinv[NN];
__device__ int    g_deg [NN];
__device__ int    g_rowstart[NN + 1];
__device__ int    g_cnt [NN];
__device__ int    g_blocksum[NBLK];
__device__ float4 g_adj [2 * NE];    // {src, eid, enorm, unused}

// ---------------- setup kernels ----------------

__global__ void k_initego(const float* __restrict__ u, const float* __restrict__ it) {
    int i = blockIdx.x * blockDim.x + threadIdx.x;
    if (i >= NN * D) return;
    float v = (i < NU * D) ? u[i] : it[i - NU * D];
    g_ego0[i] = v;
    g_all[i]  = v;
}

__global__ void k_deg(const int* __restrict__ ei) {
    int j = blockIdx.x * blockDim.x + threadIdx.x;
    if (j >= NE) return;
    atomicAdd(&g_deg[ei[j]], 1);
    atomicAdd(&g_deg[ei[NE + j]], 1);
}

__global__ void k_dinv() {
    int n = blockIdx.x * blockDim.x + threadIdx.x;
    if (n >= NN) return;
    int d = g_deg[n];
    g_dinv[n] = (d > 0) ? (1.0f / sqrtf((float)d)) : 0.0f;
}

__global__ void k_partial() {
    __shared__ int sh[1024];
    int t = threadIdx.x, n = blockIdx.x * 1024 + t;
    sh[t] = (n < NN) ? g_deg[n] : 0;
    __syncthreads();
    for (int o = 512; o > 0; o >>= 1) {
        if (t < o) sh[t] += sh[t + o];
        __syncthreads();
    }
    if (t == 0) g_blocksum[blockIdx.x] = sh[0];
}

__global__ void k_scanblocks() {
    int acc = 0;
    for (int b = 0; b < NBLK; b++) {
        int v = g_blocksum[b];
        g_blocksum[b] = acc;
        acc += v;
    }
    g_rowstart[NN] = 2 * NE;
}

__global__ void k_offsets() {
    __shared__ int sh[1024];
    int t = threadIdx.x, n = blockIdx.x * 1024 + t;
    int v = (n < NN) ? g_deg[n] : 0;
    sh[t] = v;
    __syncthreads();
    for (int o = 1; o < 1024; o <<= 1) {
        int x = (t >= o) ? sh[t - o] : 0;
        __syncthreads();
        sh[t] += x;
        __syncthreads();
    }
    if (n < NN) g_rowstart[n] = g_blocksum[blockIdx.x] + sh[t] - v;
}

// fill CSR adjacency: both directions of every edge
__global__ void k_fill(const int* __restrict__ ei) {
    int d = blockIdx.x * blockDim.x + threadIdx.x;
    if (d >= 2 * NE) return;
    int j = (d < NE) ? d : d - NE;
    int r = ei[j], c = ei[NE + j];
    int src = (d < NE) ? r : c;
    int dst = (d < NE) ? c : r;
    int pos = g_rowstart[dst] + atomicAdd(&g_cnt[dst], 1);
    g_adj[pos] = make_float4(__int_as_float(src), __int_as_float(j),
                             g_dinv[src] * g_dinv[dst], 0.0f);
}

// initial softmax of the input S -> SsmA
__global__ void k_softmax0(const float* __restrict__ S) {
    int j = blockIdx.x * blockDim.x + threadIdx.x;
    if (j >= NE) return;
    float4 s = make_float4(S[j], S[NE + j], S[2 * NE + j], S[3 * NE + j]);
    float m  = fmaxf(fmaxf(s.x, s.y), fmaxf(s.z, s.w));
    float e0 = expf(s.x - m), e1 = expf(s.y - m);
    float e2 = expf(s.z - m), e3 = expf(s.w - m);
    float r  = 1.0f / (e0 + e1 + e2 + e3);
    g_SsmA[j] = make_float4(e0 * r, e1 * r, e2 * r, e3 * r);
}

// tv for layer 0 from the initial ego (warp per node)
__global__ void k_tv0() {
    int gw = (blockIdx.x * blockDim.x + threadIdx.x) >> 5;
    if (gw >= NN) return;
    int lane = threadIdx.x & 31;
    float2 a = reinterpret_cast<const float2*>(g_ego0 + (size_t)gw * D)[lane];
    float ss = a.x * a.x + a.y * a.y;
    ss += __shfl_xor_sync(0xFFFFFFFF, ss, 1);
    ss += __shfl_xor_sync(0xFFFFFFFF, ss, 2);
    ss += __shfl_xor_sync(0xFFFFFFFF, ss, 4);
    float rinv = 1.0f / fmaxf(sqrtf(ss), 1e-12f);
    float2 o;
    o.x = tanhf(a.x * rinv);
    o.y = tanhf(a.y * rinv);
    reinterpret_cast<float2*>(g_tv0 + (size_t)gw * D)[lane] = o;
}

// ---------------- fused conv + score + softmax, one warp per node ----------------
// Phase 1 (all nodes): CSR conv reading ssm_in (dependent 16B gather, like R5),
//   xn row write; LASTIT additionally does all_embs += xn and writes the next
//   layer's tv into tv_next (double buffer).
// Phase 2 (user nodes only): this warp's adjacency list is exactly its original
//   edges (reverse copies, src=item, eid=j). acc (=xn[row]) and rinv (=rn[row])
//   are already in registers. Gathers tv[item], dots, updates S; lane 0 applies
//   softmax and writes ssm_out[j] (FINAL: raw g_S4[j] instead).
template <bool LASTIT, bool FINAL>
__global__ void k_fused(const float* __restrict__ ego, float* __restrict__ xn,
                        const float* __restrict__ tv, float* __restrict__ tv_next,
                        const float4* __restrict__ ssm_in, float4* __restrict__ ssm_out) {
    int gw = (blockIdx.x * blockDim.x + threadIdx.x) >> 5;
    if (gw >= NN) return;
    int lane = threadIdx.x & 31;
    int kf = lane >> 3;
    int s = g_rowstart[gw], e = g_rowstart[gw + 1];

    // ---- phase 1: conv ----
    float2 acc = make_float2(0.0f, 0.0f);
    float4 a0 = make_float4(0, 0, 0, 0), s0 = make_float4(0, 0, 0, 0);
    if (s < e) {
        a0 = g_adj[s];
        s0 = ssm_in[__float_as_int(a0.y)];
    }
    for (int i = s; i < e; i++) {
        float4 a1 = a0, s1 = s0;
        if (i + 1 < e) {
            a1 = g_adj[i + 1];
            s1 = ssm_in[__float_as_int(a1.y)];
        }
        int   nbr = __float_as_int(a0.x);
        float en  = a0.z;
        float2 v = reinterpret_cast<const float2*>(ego + (size_t)nbr * D)[lane];
        float smk = (kf == 0) ? s0.x : (kf == 1) ? s0.y : (kf == 2) ? s0.z : s0.w;
        float w = en * smk;
        acc.x += w * v.x;
        acc.y += w * v.y;
        a0 = a1; s0 = s1;
    }

    reinterpret_cast<float2*>(xn + (size_t)gw * D)[lane] = acc;

    // per-factor inverse norm (every lane ends with its 8-lane group's value)
    float ss = acc.x * acc.x + acc.y * acc.y;
    ss += __shfl_xor_sync(0xFFFFFFFF, ss, 1);
    ss += __shfl_xor_sync(0xFFFFFFFF, ss, 2);
    ss += __shfl_xor_sync(0xFFFFFFFF, ss, 4);
    float rinv = 1.0f / fmaxf(sqrtf(ss), 1e-12f);

    if (LASTIT) {
        float2* ap = reinterpret_cast<float2*>(g_all + (size_t)gw * D) + lane;
        float2 av = *ap;
        av.x += acc.x; av.y += acc.y;
        *ap = av;
        float2 t;
        t.x = tanhf(acc.x * rinv);
        t.y = tanhf(acc.y * rinv);
        reinterpret_cast<float2*>(tv_next + (size_t)gw * D)[lane] = t;
    }

    // ---- phase 2: score (user nodes only) ----
    if (gw >= NU) return;

    // lane 0 needs all 4 per-factor rinv values
    float r0 = __shfl_sync(0xFFFFFFFF, rinv, 0);
    float r1 = __shfl_sync(0xFFFFFFFF, rinv, 8);
    float r2 = __shfl_sync(0xFFFFFFFF, rinv, 16);
    float r3 = __shfl_sync(0xFFFFFFFF, rinv, 24);

    float4 b0 = make_float4(0, 0, 0, 0);
    if (s < e) b0 = g_adj[s];
    for (int i = s; i < e; i++) {
        float4 b1 = b0;
        if (i + 1 < e) b1 = g_adj[i + 1];
        int item = __float_as_int(b0.x);
        int eid  = __float_as_int(b0.y);
        float2 t = reinterpret_cast<const float2*>(tv + (size_t)item * D)[lane];
        float p = acc.x * t.x + acc.y * t.y;
        p += __shfl_xor_sync(0xFFFFFFFF, p, 1);
        p += __shfl_xor_sync(0xFFFFFFFF, p, 2);
        p += __shfl_xor_sync(0xFFFFFFFF, p, 4);
        float p0 = __shfl_sync(0xFFFFFFFF, p, 0);
        float p1 = __shfl_sync(0xFFFFFFFF, p, 8);
        float p2 = __shfl_sync(0xFFFFFFFF, p, 16);
        float p3 = __shfl_sync(0xFFFFFFFF, p, 24);
        if (lane == 0) {
            float4 sv = ssm_in[eid];
            sv.x += p0 * r0;
            sv.y += p1 * r1;
            sv.z += p2 * r2;
            sv.w += p3 * r3;
            if (FINAL) {
                g_S4[eid] = sv;
            } else {
                float m  = fmaxf(fmaxf(sv.x, sv.y), fmaxf(sv.z, sv.w));
                float e0 = expf(sv.x - m), e1 = expf(sv.y - m);
                float e2 = expf(sv.z - m), e3 = expf(sv.w - m);
                float rr = 1.0f / (e0 + e1 + e2 + e3);
                ssm_out[eid] = make_float4(e0 * rr, e1 * rr, e2 * rr, e3 * rr);
            }
        }
        b0 = b1;
    }
}

// output S transpose [NE,4] -> [4,NE]
__global__ void k_transS_out(float* __restrict__ outS) {
    int j = blockIdx.x * blockDim.x + threadIdx.x;
    if (j >= NE) return;
    float4 s = g_S4[j];
    outS[j]          = s.x;
    outS[NE + j]     = s.y;
    outS[2 * NE + j] = s.z;
    outS[3 * NE + j] = s.w;
}

// ---------------- host orchestration ----------------

extern "C" void kernel_launch(void* const* d_in, const int* in_sizes, int n_in,
                              void* d_out, int out_size) {
    const float* user = (const float*)d_in[0];
    const float* item = (const float*)d_in[1];
    const float* Sin  = (const float*)d_in[2];
    const int*   ei   = (const int*)d_in[3];
    float* out = (float*)d_out;

    void *p_deg, *p_cnt, *p_ego0, *p_ego1, *p_all, *p_tv0, *p_tv1, *p_ssmA, *p_ssmB;
    cudaGetSymbolAddress(&p_deg,  g_deg);
    cudaGetSymbolAddress(&p_cnt,  g_cnt);
    cudaGetSymbolAddress(&p_ego0, g_ego0);
    cudaGetSymbolAddress(&p_ego1, g_ego1);
    cudaGetSymbolAddress(&p_all,  g_all);
    cudaGetSymbolAddress(&p_tv0,  g_tv0);
    cudaGetSymbolAddress(&p_tv1,  g_tv1);
    cudaGetSymbolAddress(&p_ssmA, g_SsmA);
    cudaGetSymbolAddress(&p_ssmB, g_SsmB);

    const int T = 256;
    const int gElem  = (NN * D + T - 1) / T;
    const int gNode  = (NN + T - 1) / T;
    const int gEdge  = (NE + T - 1) / T;
    const int gDir   = (2 * NE + T - 1) / T;
    const int gNodeW = (NN * 32 + T - 1) / T;

    // ---- setup ----
    cudaMemsetAsync(p_deg, 0, NN * sizeof(int), 0);
    cudaMemsetAsync(p_cnt, 0, NN * sizeof(int), 0);
    k_initego<<<gElem, T>>>(user, item);
    k_deg<<<gEdge, T>>>(ei);
    k_dinv<<<gNode, T>>>();
    k_partial<<<NBLK, 1024>>>();
    k_scanblocks<<<1, 1>>>();
    k_offsets<<<NBLK, 1024>>>();
    k_fill<<<gDir, T>>>(ei);
    k_softmax0<<<gEdge, T>>>(Sin);
    k_tv0<<<gNodeW, T>>>();

    // ---- 2 layers x 2 routing iterations, 1 fused kernel each ----
    float*  ego  = (float*)p_ego0;
    float*  xn   = (float*)p_ego1;
    float*  tv   = (float*)p_tv0;
    float*  tvn  = (float*)p_tv1;
    float4* ssmA = (float4*)p_ssmA;
    float4* ssmB = (float4*)p_ssmB;

    // layer 0
    k_fused<false, false><<<gNodeW, T>>>(ego, xn, tv, tvn, ssmA, ssmB);
    { float4* t = ssmA; ssmA = ssmB; ssmB = t; }
    k_fused<true,  false><<<gNodeW, T>>>(ego, xn, tv, tvn, ssmA, ssmB);
    { float4* t = ssmA; ssmA = ssmB; ssmB = t; }
    { float* t = ego; ego = xn; xn = t; t = tv; tv = tvn; tvn = t; }
    // layer 1
    k_fused<false, false><<<gNodeW, T>>>(ego, xn, tv, tvn, ssmA, ssmB);
    { float4* t = ssmA; ssmA = ssmB; ssmB = t; }
    k_fused<true,  true ><<<gNodeW, T>>>(ego, xn, tv, tvn, ssmA, ssmB);

    // ---- output: [user_all | item_all | S(4,NE)] ----
    cudaMemcpyAsync(out, p_all, (size_t)NN * D * sizeof(float),
                    cudaMemcpyDeviceToDevice, 0);
    k_transS_out<<<gEdge, T>>>(out + (size_t)NN * D);
}

// round 8
// speedup vs baseline: 1.6907x; 1.2024x over previous
#include <cuda_runtime.h>
#include <math.h>

// Problem constants (fixed by the dataset)
#define NU 60000
#define NI 40000
#define NN 100000     // NU + NI
#define NE 500000
#define D  64
#define NF 4
#define NBLK 98       // ceil(NN/1024) for the scan
#define FULLM 0xFFFFFFFFu

// ---------------- static device scratch ----------------
__device__ float  g_ego0[NN * D];
__device__ float  g_ego1[NN * D];
__device__ float  g_all [NN * D];
__device__ float  g_tv0 [NN * D];    // tv double buffer
__device__ float  g_tv1 [NN * D];
__device__ float4 g_S4  [NE];        // raw S (written only on the final iteration)
__device__ float4 g_SsmA[NE];        // softmax(S) double buffer
__device__ float4 g_SsmB[NE];
__device__ float  g_dinv[NN];
__device__ int    g_deg [NN];
__device__ int    g_rowstart[NN + 1];
__device__ int    g_cnt [NN];
__device__ int    g_blocksum[NBLK];
__device__ float4 g_adj [2 * NE];    // {src, eid, enorm, unused}

// ---------------- setup kernels ----------------

__global__ void k_initego(const float* __restrict__ u, const float* __restrict__ it) {
    int i = blockIdx.x * blockDim.x + threadIdx.x;
    if (i >= NN * D) return;
    float v = (i < NU * D) ? u[i] : it[i - NU * D];
    g_ego0[i] = v;
    g_all[i]  = v;
}

__global__ void k_deg(const int* __restrict__ ei) {
    int j = blockIdx.x * blockDim.x + threadIdx.x;
    if (j >= NE) return;
    atomicAdd(&g_deg[ei[j]], 1);
    atomicAdd(&g_deg[ei[NE + j]], 1);
}

__global__ void k_dinv() {
    int n = blockIdx.x * blockDim.x + threadIdx.x;
    if (n >= NN) return;
    int d = g_deg[n];
    g_dinv[n] = (d > 0) ? (1.0f / sqrtf((float)d)) : 0.0f;
}

__global__ void k_partial() {
    __shared__ int sh[1024];
    int t = threadIdx.x, n = blockIdx.x * 1024 + t;
    sh[t] = (n < NN) ? g_deg[n] : 0;
    __syncthreads();
    for (int o = 512; o > 0; o >>= 1) {
        if (t < o) sh[t] += sh[t + o];
        __syncthreads();
    }
    if (t == 0) g_blocksum[blockIdx.x] = sh[0];
}

__global__ void k_scanblocks() {
    int acc = 0;
    for (int b = 0; b < NBLK; b++) {
        int v = g_blocksum[b];
        g_blocksum[b] = acc;
        acc += v;
    }
    g_rowstart[NN] = 2 * NE;
}

__global__ void k_offsets() {
    __shared__ int sh[1024];
    int t = threadIdx.x, n = blockIdx.x * 1024 + t;
    int v = (n < NN) ? g_deg[n] : 0;
    sh[t] = v;
    __syncthreads();
    for (int o = 1; o < 1024; o <<= 1) {
        int x = (t >= o) ? sh[t - o] : 0;
        __syncthreads();
        sh[t] += x;
        __syncthreads();
    }
    if (n < NN) g_rowstart[n] = g_blocksum[blockIdx.x] + sh[t] - v;
}

// fill CSR adjacency: both directions of every edge
__global__ void k_fill(const int* __restrict__ ei) {
    int d = blockIdx.x * blockDim.x + threadIdx.x;
    if (d >= 2 * NE) return;
    int j = (d < NE) ? d : d - NE;
    int r = ei[j], c = ei[NE + j];
    int src = (d < NE) ? r : c;
    int dst = (d < NE) ? c : r;
    int pos = g_rowstart[dst] + atomicAdd(&g_cnt[dst], 1);
    g_adj[pos] = make_float4(__int_as_float(src), __int_as_float(j),
                             g_dinv[src] * g_dinv[dst], 0.0f);
}

// initial softmax of the input S -> SsmA
__global__ void k_softmax0(const float* __restrict__ S) {
    int j = blockIdx.x * blockDim.x + threadIdx.x;
    if (j >= NE) return;
    float4 s = make_float4(S[j], S[NE + j], S[2 * NE + j], S[3 * NE + j]);
    float m  = fmaxf(fmaxf(s.x, s.y), fmaxf(s.z, s.w));
    float e0 = expf(s.x - m), e1 = expf(s.y - m);
    float e2 = expf(s.z - m), e3 = expf(s.w - m);
    float r  = 1.0f / (e0 + e1 + e2 + e3);
    g_SsmA[j] = make_float4(e0 * r, e1 * r, e2 * r, e3 * r);
}

// tv for layer 0 from the initial ego (warp per node)
__global__ void k_tv0() {
    int gw = (blockIdx.x * blockDim.x + threadIdx.x) >> 5;
    if (gw >= NN) return;
    int lane = threadIdx.x & 31;
    float2 a = reinterpret_cast<const float2*>(g_ego0 + (size_t)gw * D)[lane];
    float ss = a.x * a.x + a.y * a.y;
    ss += __shfl_xor_sync(FULLM, ss, 1);
    ss += __shfl_xor_sync(FULLM, ss, 2);
    ss += __shfl_xor_sync(FULLM, ss, 4);
    float rinv = 1.0f / fmaxf(sqrtf(ss), 1e-12f);
    float2 o;
    o.x = tanhf(a.x * rinv);
    o.y = tanhf(a.y * rinv);
    reinterpret_cast<float2*>(g_tv0 + (size_t)gw * D)[lane] = o;
}

// broadcast source lane j's per-factor weight vector; return this lane's factor
__device__ __forceinline__ float bcast_w(float4 w4, int j, int kf) {
    float wx = __shfl_sync(FULLM, w4.x, j);
    float wy = __shfl_sync(FULLM, w4.y, j);
    float wz = __shfl_sync(FULLM, w4.z, j);
    float ww = __shfl_sync(FULLM, w4.w, j);
    return (kf == 0) ? wx : (kf == 1) ? wy : (kf == 2) ? wz : ww;
}

// ---------------- fused conv + score + softmax, one warp per node ----------------
// Phase 1 (all nodes): warp batch-loads up to 32 adjacency entries (coalesced)
//   and 32 parallel ssm gathers, then the inner loop is shuffle-broadcast +
//   ego-row gather only, unrolled x4 for MLP.
// Phase 2 (user warps): same batching; score reduce per edge; update + softmax
//   + store done LANE-PARALLEL (lane j owns edge j of the batch).
template <bool LASTIT, bool FINAL>
__global__ void __launch_bounds__(256)
k_fused(const float* __restrict__ ego, float* __restrict__ xn,
        const float* __restrict__ tv, float* __restrict__ tv_next,
        const float4* __restrict__ ssm_in, float4* __restrict__ ssm_out) {
    int gw = (blockIdx.x * blockDim.x + threadIdx.x) >> 5;
    if (gw >= NN) return;
    int lane = threadIdx.x & 31;
    int kf = lane >> 3;
    int s = g_rowstart[gw], e = g_rowstart[gw + 1];

    // ---- phase 1: conv ----
    float2 acc = make_float2(0.0f, 0.0f);
    for (int b = s; b < e; b += 32) {
        int n = min(32, e - b);
        int src = 0;
        float4 w4 = make_float4(0, 0, 0, 0);
        if (lane < n) {
            float4 a = g_adj[b + lane];                 // coalesced batch load
            src = __float_as_int(a.x);
            float4 sm = ssm_in[__float_as_int(a.y)];    // 32 gathers in flight
            w4 = make_float4(sm.x * a.z, sm.y * a.z, sm.z * a.z, sm.w * a.z);
        }
        int j = 0;
        for (; j + 4 <= n; j += 4) {
            int s0 = __shfl_sync(FULLM, src, j);
            int s1 = __shfl_sync(FULLM, src, j + 1);
            int s2 = __shfl_sync(FULLM, src, j + 2);
            int s3 = __shfl_sync(FULLM, src, j + 3);
            float2 v0 = *reinterpret_cast<const float2*>(ego + (size_t)s0 * D + lane * 2);
            float2 v1 = *reinterpret_cast<const float2*>(ego + (size_t)s1 * D + lane * 2);
            float2 v2 = *reinterpret_cast<const float2*>(ego + (size_t)s2 * D + lane * 2);
            float2 v3 = *reinterpret_cast<const float2*>(ego + (size_t)s3 * D + lane * 2);
            float w0 = bcast_w(w4, j,     kf);
            float w1 = bcast_w(w4, j + 1, kf);
            float w2 = bcast_w(w4, j + 2, kf);
            float w3 = bcast_w(w4, j + 3, kf);
            acc.x += w0 * v0.x; acc.y += w0 * v0.y;
            acc.x += w1 * v1.x; acc.y += w1 * v1.y;
            acc.x += w2 * v2.x; acc.y += w2 * v2.y;
            acc.x += w3 * v3.x; acc.y += w3 * v3.y;
        }
        for (; j < n; j++) {
            int sj = __shfl_sync(FULLM, src, j);
            float2 v = *reinterpret_cast<const float2*>(ego + (size_t)sj * D + lane * 2);
            float wj = bcast_w(w4, j, kf);
            acc.x += wj * v.x; acc.y += wj * v.y;
        }
    }

    reinterpret_cast<float2*>(xn + (size_t)gw * D)[lane] = acc;

    // per-factor inverse norm (every lane ends with its 8-lane group's value)
    float ss = acc.x * acc.x + acc.y * acc.y;
    ss += __shfl_xor_sync(FULLM, ss, 1);
    ss += __shfl_xor_sync(FULLM, ss, 2);
    ss += __shfl_xor_sync(FULLM, ss, 4);
    float rinv = 1.0f / fmaxf(sqrtf(ss), 1e-12f);

    if (LASTIT) {
        float2* ap = reinterpret_cast<float2*>(g_all + (size_t)gw * D) + lane;
        float2 av = *ap;
        av.x += acc.x; av.y += acc.y;
        *ap = av;
        float2 t;
        t.x = tanhf(acc.x * rinv);
        t.y = tanhf(acc.y * rinv);
        reinterpret_cast<float2*>(tv_next + (size_t)gw * D)[lane] = t;
    }

    // ---- phase 2: score (user nodes only) ----
    if (gw >= NU) return;

    float r0 = __shfl_sync(FULLM, rinv, 0);
    float r1 = __shfl_sync(FULLM, rinv, 8);
    float r2 = __shfl_sync(FULLM, rinv, 16);
    float r3 = __shfl_sync(FULLM, rinv, 24);

    for (int b = s; b < e; b += 32) {
        int n = min(32, e - b);
        int item = 0, eid = 0;
        float4 svr = make_float4(0, 0, 0, 0);
        if (lane < n) {
            float4 a = g_adj[b + lane];
            item = __float_as_int(a.x);
            eid  = __float_as_int(a.y);
            svr  = ssm_in[eid];
        }
        float4 pp = make_float4(0, 0, 0, 0);
        int j = 0;
        for (; j + 2 <= n; j += 2) {
            int i0 = __shfl_sync(FULLM, item, j);
            int i1 = __shfl_sync(FULLM, item, j + 1);
            float2 t0 = *reinterpret_cast<const float2*>(tv + (size_t)i0 * D + lane * 2);
            float2 t1 = *reinterpret_cast<const float2*>(tv + (size_t)i1 * D + lane * 2);
            float pa = acc.x * t0.x + acc.y * t0.y;
            float pb = acc.x * t1.x + acc.y * t1.y;
            pa += __shfl_xor_sync(FULLM, pa, 1);  pb += __shfl_xor_sync(FULLM, pb, 1);
            pa += __shfl_xor_sync(FULLM, pa, 2);  pb += __shfl_xor_sync(FULLM, pb, 2);
            pa += __shfl_xor_sync(FULLM, pa, 4);  pb += __shfl_xor_sync(FULLM, pb, 4);
            float qa0 = __shfl_sync(FULLM, pa, 0),  qa1 = __shfl_sync(FULLM, pa, 8);
            float qa2 = __shfl_sync(FULLM, pa, 16), qa3 = __shfl_sync(FULLM, pa, 24);
            float qb0 = __shfl_sync(FULLM, pb, 0),  qb1 = __shfl_sync(FULLM, pb, 8);
            float qb2 = __shfl_sync(FULLM, pb, 16), qb3 = __shfl_sync(FULLM, pb, 24);
            if (lane == j)     pp = make_float4(qa0, qa1, qa2, qa3);
            if (lane == j + 1) pp = make_float4(qb0, qb1, qb2, qb3);
        }
        for (; j < n; j++) {
            int ij = __shfl_sync(FULLM, item, j);
            float2 t = *reinterpret_cast<const float2*>(tv + (size_t)ij * D + lane * 2);
            float p = acc.x * t.x + acc.y * t.y;
            p += __shfl_xor_sync(FULLM, p, 1);
            p += __shfl_xor_sync(FULLM, p, 2);
            p += __shfl_xor_sync(FULLM, p, 4);
            float q0 = __shfl_sync(FULLM, p, 0),  q1 = __shfl_sync(FULLM, p, 8);
            float q2 = __shfl_sync(FULLM, p, 16), q3 = __shfl_sync(FULLM, p, 24);
            if (lane == j) pp = make_float4(q0, q1, q2, q3);
        }
        if (lane < n) {
            float4 sv = make_float4(svr.x + pp.x * r0, svr.y + pp.y * r1,
                                    svr.z + pp.z * r2, svr.w + pp.w * r3);
            if (FINAL) {
                g_S4[eid] = sv;
            } else {
                // lane-parallel softmax for the next iteration's conv
                float m  = fmaxf(fmaxf(sv.x, sv.y), fmaxf(sv.z, sv.w));
                float e0 = expf(sv.x - m), e1 = expf(sv.y - m);
                float e2 = expf(sv.z - m), e3 = expf(sv.w - m);
                float rr = 1.0f / (e0 + e1 + e2 + e3);
                ssm_out[eid] = make_float4(e0 * rr, e1 * rr, e2 * rr, e3 * rr);
            }
        }
    }
}

// output S transpose [NE,4] -> [4,NE]
__global__ void k_transS_out(float* __restrict__ outS) {
    int j = blockIdx.x * blockDim.x + threadIdx.x;
    if (j >= NE) return;
    float4 s = g_S4[j];
    outS[j]          = s.x;
    outS[NE + j]     = s.y;
    outS[2 * NE + j] = s.z;
    outS[3 * NE + j] = s.w;
}

// ---------------- host orchestration ----------------

extern "C" void kernel_launch(void* const* d_in, const int* in_sizes, int n_in,
                              void* d_out, int out_size) {
    const float* user = (const float*)d_in[0];
    const float* item = (const float*)d_in[1];
    const float* Sin  = (const float*)d_in[2];
    const int*   ei   = (const int*)d_in[3];
    float* out = (float*)d_out;

    void *p_deg, *p_cnt, *p_ego0, *p_ego1, *p_all, *p_tv0, *p_tv1, *p_ssmA, *p_ssmB;
    cudaGetSymbolAddress(&p_deg,  g_deg);
    cudaGetSymbolAddress(&p_cnt,  g_cnt);
    cudaGetSymbolAddress(&p_ego0, g_ego0);
    cudaGetSymbolAddress(&p_ego1, g_ego1);
    cudaGetSymbolAddress(&p_all,  g_all);
    cudaGetSymbolAddress(&p_tv0,  g_tv0);
    cudaGetSymbolAddress(&p_tv1,  g_tv1);
    cudaGetSymbolAddress(&p_ssmA, g_SsmA);
    cudaGetSymbolAddress(&p_ssmB, g_SsmB);

    const int T = 256;
    const int gElem  = (NN * D + T - 1) / T;
    const int gNode  = (NN + T - 1) / T;
    const int gEdge  = (NE + T - 1) / T;
    const int gDir   = (2 * NE + T - 1) / T;
    const int gNodeW = (NN * 32 + T - 1) / T;

    // ---- setup ----
    cudaMemsetAsync(p_deg, 0, NN * sizeof(int), 0);
    cudaMemsetAsync(p_cnt, 0, NN * sizeof(int), 0);
    k_initego<<<gElem, T>>>(user, item);
    k_deg<<<gEdge, T>>>(ei);
    k_dinv<<<gNode, T>>>();
    k_partial<<<NBLK, 1024>>>();
    k_scanblocks<<<1, 1>>>();
    k_offsets<<<NBLK, 1024>>>();
    k_fill<<<gDir, T>>>(ei);
    k_softmax0<<<gEdge, T>>>(Sin);
    k_tv0<<<gNodeW, T>>>();

    // ---- 2 layers x 2 routing iterations, 1 fused kernel each ----
    float*  ego  = (float*)p_ego0;
    float*  xn   = (float*)p_ego1;
    float*  tv   = (float*)p_tv0;
    float*  tvn  = (float*)p_tv1;
    float4* ssmA = (float4*)p_ssmA;
    float4* ssmB = (float4*)p_ssmB;

    // layer 0
    k_fused<false, false><<<gNodeW, T>>>(ego, xn, tv, tvn, ssmA, ssmB);
    { float4* t = ssmA; ssmA = ssmB; ssmB = t; }
    k_fused<true,  false><<<gNodeW, T>>>(ego, xn, tv, tvn, ssmA, ssmB);
    { float4* t = ssmA; ssmA = ssmB; ssmB = t; }
    { float* t = ego; ego = xn; xn = t; t = tv; tv = tvn; tvn = t; }
    // layer 1
    k_fused<false, false><<<gNodeW, T>>>(ego, xn, tv, tvn, ssmA, ssmB);
    { float4* t = ssmA; ssmA = ssmB; ssmB = t; }
    k_fused<true,  true ><<<gNodeW, T>>>(ego, xn, tv, tvn, ssmA, ssmB);

    // ---- output: [user_all | item_all | S(4,NE)] ----
    cudaMemcpyAsync(out, p_all, (size_t)NN * D * sizeof(float),
                    cudaMemcpyDeviceToDevice, 0);
    k_transS_out<<<gEdge, T>>>(out + (size_t)NN * D);
}